// round 3
// baseline (speedup 1.0000x reference)
#include <cuda_runtime.h>
#include <math.h>
#include <stdint.h>

#define HH 40
#define WW 40
#define CIN 2048
#define NPIX 1600
#define CMID 256
#define NA 5
#define NBOX 8000
#define NWORD 125
#define MAXDET 300

#define KC 16          // k per chunk
#define NCH (CIN / KC) // 128 chunks
#define PADK 20        // padded k row (floats), conflict-free & 16B-multiple
#define PLANEF (128 * PADK)      // 2560 floats per plane tile
#define BUFF (4 * PLANEF)        // 10240 floats per buffer (AHI,ALO,BHI,BLO)
#define SMEM_BYTES (2 * BUFF * 4)  // 81920

// ---------------- device scratch (static, no allocation) ----------------
__device__ float g_ahi[NPIX * CIN];
__device__ float g_alo[NPIX * CIN];
__device__ float g_whi[9 * CMID * CIN];   // [tap][n][k]
__device__ float g_wlo[9 * CMID * CIN];
__device__ float g_partial[9 * NPIX * CMID];
__device__ float g_x[NPIX * CMID];
__device__ float g_scores[NBOX];
__device__ float g_boxes[NBOX * 4];
__device__ float g_boxsorted[NBOX * 4];
__device__ float g_rois[MAXDET * 4];

// ---------------- helpers ----------------
__device__ __forceinline__ uint32_t smem_u32(const void* p) {
  uint32_t a;
  asm("{ .reg .u64 t; cvta.to.shared.u64 t, %1; cvt.u32.u64 %0, t; }" : "=r"(a) : "l"(p));
  return a;
}
__device__ __forceinline__ float f2tf32(float f) {
  uint32_t r;
  asm("cvt.rna.tf32.f32 %0, %1;" : "=r"(r) : "f"(f));
  return __uint_as_float(r);
}
__device__ __forceinline__ void cp16(uint32_t dst, const void* src, uint32_t sz) {
  asm volatile("cp.async.ca.shared.global [%0], [%1], 16, %2;" ::"r"(dst), "l"(src), "r"(sz)
               : "memory");
}
#define CP_COMMIT() asm volatile("cp.async.commit_group;" ::: "memory")
#define CP_WAIT1() asm volatile("cp.async.wait_group 1;" ::: "memory")
#define CP_WAIT0() asm volatile("cp.async.wait_group 0;" ::: "memory")

__device__ __forceinline__ void mma_tf32(float* c, uint32_t a0, uint32_t a1, uint32_t a2,
                                         uint32_t a3, uint32_t b0, uint32_t b1) {
  asm volatile(
      "mma.sync.aligned.m16n8k8.row.col.f32.tf32.tf32.f32 "
      "{%0,%1,%2,%3}, {%4,%5,%6,%7}, {%8,%9}, {%0,%1,%2,%3};"
      : "+f"(c[0]), "+f"(c[1]), "+f"(c[2]), "+f"(c[3])
      : "r"(a0), "r"(a1), "r"(a2), "r"(a3), "r"(b0), "r"(b1));
}

// ---------------- K0a: feature fp32 -> tf32 hi/lo planes ----------------
__global__ __launch_bounds__(256) void feat_split_kernel(const float* __restrict__ feat) {
  int i = blockIdx.x * 256 + threadIdx.x;
  float f = feat[i];
  float hi = f2tf32(f);
  float lo = f2tf32(f - hi);
  g_ahi[i] = hi;
  g_alo[i] = lo;
}

// ---------------- K0b: weights fp32 [tap][k][n] -> hi/lo [tap][n][k] ----------------
__global__ __launch_bounds__(1024) void w_split_kernel(const float* __restrict__ w) {
  __shared__ float th[32][33];
  __shared__ float tl[32][33];
  const int tap = blockIdx.x;
  const int k0 = blockIdx.y * 32;
  const int n0 = blockIdx.z * 32;
  const int tx = threadIdx.x, ty = threadIdx.y;
  float f = w[((size_t)tap * CIN + k0 + ty) * CMID + n0 + tx];
  float hi = f2tf32(f);
  float lo = f2tf32(f - hi);
  th[ty][tx] = hi;
  tl[ty][tx] = lo;
  __syncthreads();
  size_t dst = (size_t)(tap * CMID + n0 + ty) * CIN + k0 + tx;
  g_whi[dst] = th[tx][ty];
  g_wlo[dst] = tl[tx][ty];
}

// ---------------- K1: 3xTF32 mma.sync conv GEMM ----------------
// CTA: M=128 pixels x N=128 channels x one tap. 8 warps, each 64x32.
__global__ __launch_bounds__(256) void conv_mma_kernel() {
  extern __shared__ float dsm[];
  const uint32_t sbase = smem_u32(dsm);
  const uint32_t* su = (const uint32_t*)dsm;

  const int mt = blockIdx.x;   // 0..12
  const int nt = blockIdx.y;   // 0..1
  const int tap = blockIdx.z;  // 0..8
  const int ky = tap / 3, kx = tap % 3;
  const int tid = threadIdx.x;
  const int warp = tid >> 5;
  const int lane = tid & 31;
  const int wm = warp & 1;   // m half (64 rows)
  const int wn = warp >> 1;  // n quarter (32 cols)
  const int lr = lane >> 2, lq = lane & 3;

  // ---- load mapping: row = tid>>1 (0..127), half = tid&1 (k offset 0/8)
  const int row = tid >> 1;
  const int half = tid & 1;
  const int m = mt * 128 + row;
  bool aval = false;
  int p2 = 0;
  if (m < NPIX) {
    int y = m / WW, x = m % WW;
    int py = y + ky - 1, px = x + kx - 1;
    aval = (py >= 0 && py < HH && px >= 0 && px < WW);
    p2 = py * WW + px;
  }
  const uint32_t asz = aval ? 16u : 0u;
  const float* pahi = g_ahi + (size_t)(aval ? p2 : 0) * CIN + half * 8;
  const float* palo = g_alo + (size_t)(aval ? p2 : 0) * CIN + half * 8;
  const size_t boff = (size_t)(tap * CMID + nt * 128 + row) * CIN + half * 8;
  const float* pbhi = g_whi + boff;
  const float* pblo = g_wlo + boff;
  // smem dst (bytes) for this thread within a buffer
  const uint32_t drow = (uint32_t)(row * PADK + half * 8) * 4;

  float c[4][4][4];
#pragma unroll
  for (int i = 0; i < 4; i++)
#pragma unroll
    for (int j = 0; j < 4; j++)
#pragma unroll
      for (int r2 = 0; r2 < 4; r2++) c[i][j][r2] = 0.f;

  // prologue: issue chunk 0 into buffer 0
  {
    uint32_t b0 = sbase + drow;
#pragma unroll
    for (int i = 0; i < 2; i++) {
      cp16(b0 + 0 * PLANEF * 4 + i * 16, pahi + i * 4, asz);
      cp16(b0 + 1 * PLANEF * 4 + i * 16, palo + i * 4, asz);
      cp16(b0 + 2 * PLANEF * 4 + i * 16, pbhi + i * 4, 16u);
      cp16(b0 + 3 * PLANEF * 4 + i * 16, pblo + i * 4, 16u);
    }
    CP_COMMIT();
  }

#pragma unroll 1
  for (int cch = 0; cch < NCH; cch++) {
    if (cch + 1 < NCH) {
      const int k0 = (cch + 1) * KC;
      uint32_t bb = sbase + ((cch + 1) & 1) * (uint32_t)(BUFF * 4) + drow;
#pragma unroll
      for (int i = 0; i < 2; i++) {
        cp16(bb + 0 * PLANEF * 4 + i * 16, pahi + k0 + i * 4, asz);
        cp16(bb + 1 * PLANEF * 4 + i * 16, palo + k0 + i * 4, asz);
        cp16(bb + 2 * PLANEF * 4 + i * 16, pbhi + k0 + i * 4, 16u);
        cp16(bb + 3 * PLANEF * 4 + i * 16, pblo + k0 + i * 4, 16u);
      }
      CP_COMMIT();
      CP_WAIT1();
    } else {
      CP_WAIT0();
    }
    __syncthreads();

    const int bufo = (cch & 1) * BUFF;
#pragma unroll
    for (int ks = 0; ks < 2; ks++) {
      const int kk = ks * 8 + lq;
      // B fragments: 4 n-tiles, hi+lo
      uint32_t bh[4][2], bl[4][2];
#pragma unroll
      for (int ntl = 0; ntl < 4; ntl++) {
        const int nrow = wn * 32 + ntl * 8 + lr;
        const int ba = bufo + 2 * PLANEF + nrow * PADK + kk;
        bh[ntl][0] = su[ba];
        bh[ntl][1] = su[ba + 4];
        const int bb2 = ba + PLANEF;
        bl[ntl][0] = su[bb2];
        bl[ntl][1] = su[bb2 + 4];
      }
#pragma unroll
      for (int mtl = 0; mtl < 4; mtl++) {
        const int mrow = wm * 64 + mtl * 16 + lr;
        const int aa = bufo + mrow * PADK + kk;
        uint32_t ah0 = su[aa], ah1 = su[aa + 8 * PADK];
        uint32_t ah2 = su[aa + 4], ah3 = su[aa + 8 * PADK + 4];
        const int al = aa + PLANEF;
        uint32_t al0 = su[al], al1 = su[al + 8 * PADK];
        uint32_t al2 = su[al + 4], al3 = su[al + 8 * PADK + 4];
#pragma unroll
        for (int ntl = 0; ntl < 4; ntl++) {
          mma_tf32(c[mtl][ntl], ah0, ah1, ah2, ah3, bh[ntl][0], bh[ntl][1]);
          mma_tf32(c[mtl][ntl], ah0, ah1, ah2, ah3, bl[ntl][0], bl[ntl][1]);
          mma_tf32(c[mtl][ntl], al0, al1, al2, al3, bh[ntl][0], bh[ntl][1]);
        }
      }
    }
    __syncthreads();
  }

  // epilogue: write partials
  float* base = g_partial + (size_t)tap * (NPIX * CMID);
#pragma unroll
  for (int mtl = 0; mtl < 4; mtl++) {
    const int r0 = mt * 128 + wm * 64 + mtl * 16 + lr;
#pragma unroll
    for (int ntl = 0; ntl < 4; ntl++) {
      const int col = nt * 128 + wn * 32 + ntl * 8 + 2 * lq;
      if (r0 < NPIX)
        *(float2*)&base[(size_t)r0 * CMID + col] = make_float2(c[mtl][ntl][0], c[mtl][ntl][1]);
      if (r0 + 8 < NPIX)
        *(float2*)&base[(size_t)(r0 + 8) * CMID + col] =
            make_float2(c[mtl][ntl][2], c[mtl][ntl][3]);
    }
  }
}

// ---------------- K2: reduce 9 partials + bias + relu ----------------
__global__ __launch_bounds__(256) void reduce_bias_relu(const float* __restrict__ bias) {
  int i = blockIdx.x * 256 + threadIdx.x;
  float s = bias[i & 255];
#pragma unroll
  for (int t = 0; t < 9; t++) s += g_partial[(size_t)t * (NPIX * CMID) + i];
  g_x[i] = fmaxf(s, 0.f);
}

// ---------------- K3: 1x1 heads + score + anchor decode ----------------
__global__ __launch_bounds__(32) void head_conv_kernel(
    const float* __restrict__ cls_w, const float* __restrict__ cls_b,
    const float* __restrict__ reg_w, const float* __restrict__ reg_b) {
  const int p = blockIdx.x;
  const int lane = threadIdx.x;
  const float* xr = g_x + (size_t)p * CMID;
  float acc[30];
#pragma unroll
  for (int o = 0; o < 30; o++) acc[o] = 0.f;
  for (int k = lane; k < CMID; k += 32) {
    float xv = xr[k];
    const float* wc = cls_w + (size_t)k * 10;
#pragma unroll
    for (int o = 0; o < 10; o++) acc[o] = fmaf(xv, wc[o], acc[o]);
    const float* wr = reg_w + (size_t)k * 20;
#pragma unroll
    for (int o = 0; o < 20; o++) acc[10 + o] = fmaf(xv, wr[o], acc[10 + o]);
  }
#pragma unroll
  for (int o = 0; o < 30; o++) {
#pragma unroll
    for (int s = 16; s > 0; s >>= 1) acc[o] += __shfl_xor_sync(0xffffffffu, acc[o], s);
  }
  if (lane < NA) {
    const int a = lane;
    float l0 = acc[2 * a + 0] + cls_b[2 * a + 0];
    float l1 = acc[2 * a + 1] + cls_b[2 * a + 1];
    float score = 1.f / (1.f + expf(l0 - l1));
    float d0 = acc[10 + 4 * a + 0] + reg_b[4 * a + 0];
    float d1 = acc[10 + 4 * a + 1] + reg_b[4 * a + 1];
    float d2 = acc[10 + 4 * a + 2] + reg_b[4 * a + 2];
    float d3 = acc[10 + 4 * a + 3] + reg_b[4 * a + 3];
    float base = 32.f * (float)(1 << a);
    float wdt = expf(d2) * base;
    float hgt = expf(d3) * base;
    float xc = (float)(p % WW) + d0;
    float yc = (float)(p / WW) + d1;
    const int n = p * NA + a;
    g_scores[n] = score;
    float4 b = make_float4(xc - 0.5f * wdt, yc - 0.5f * hgt,
                           xc + 0.5f * wdt, yc + 0.5f * hgt);
    *(float4*)&g_boxes[n * 4] = b;
  }
}

// ---------------- K4: single-block bitonic sort of 8192 64-bit keys ----------------
__global__ __launch_bounds__(1024) void sort_kernel() {
  extern __shared__ unsigned long long skey[];
  const int t = threadIdx.x;
  for (int i = t; i < 8192; i += 1024) {
    unsigned long long kv;
    if (i < NBOX) {
      unsigned u = __float_as_uint(g_scores[i]);
      unsigned ou = (u & 0x80000000u) ? ~u : (u | 0x80000000u);
      kv = ((unsigned long long)(~ou) << 32) | (unsigned)i;
    } else {
      kv = 0xFFFFFFFFFFFFFFFFull;
    }
    skey[i] = kv;
  }
  __syncthreads();
  for (int k = 2; k <= 8192; k <<= 1) {
    for (int j = k >> 1; j > 0; j >>= 1) {
      for (int i = t; i < 8192; i += 1024) {
        int ixj = i ^ j;
        if (ixj > i) {
          unsigned long long a = skey[i], b = skey[ixj];
          bool up = (i & k) == 0;
          if ((a > b) == up) { skey[i] = b; skey[ixj] = a; }
        }
      }
      __syncthreads();
    }
  }
  for (int i = t; i < NBOX; i += 1024) {
    int idx = (int)(skey[i] & 0xFFFFFFFFull);
    *(float4*)&g_boxsorted[i * 4] = *(const float4*)&g_boxes[idx * 4];
  }
}

// ---------------- K5: greedy NMS ----------------
__global__ __launch_bounds__(1024) void nms_kernel() {
  extern __shared__ float sb[];
  float* bx1 = sb;
  float* by1 = sb + NBOX;
  float* bx2 = sb + 2 * NBOX;
  float* by2 = sb + 3 * NBOX;
  float* bar = sb + 4 * NBOX;
  __shared__ unsigned long long remv[NWORD];
  __shared__ int ssel[MAXDET];
  __shared__ int s_next;
  const int t = threadIdx.x;
  for (int i = t; i < NBOX; i += 1024) {
    float4 b = *(const float4*)&g_boxsorted[i * 4];
    bx1[i] = b.x; by1[i] = b.y; bx2[i] = b.z; by2[i] = b.w;
    bar[i] = (b.z - b.x) * (b.w - b.y);
  }
  if (t < NWORD) remv[t] = 0ull;
  __syncthreads();

  int count = 0, cur = 0;
  for (;;) {
    if (t == 0) s_next = 0x7FFFFFFF;
    __syncthreads();
    const int wstart = cur >> 6;
    if (t >= wstart && t < NWORD) {
      unsigned long long mw = ~remv[t];
      if (t == wstart) mw &= (~0ull) << (cur & 63);
      if (mw) atomicMin(&s_next, (t << 6) + (__ffsll((long long)mw) - 1));
    }
    __syncthreads();
    const int i = s_next;
    if (i == 0x7FFFFFFF) break;
    if (t == 0) ssel[count] = i;
    count++;
    const float ix1 = bx1[i], iy1 = by1[i], ix2 = bx2[i], iy2 = by2[i], ia = bar[i];
    for (int j = i + 1 + t; j < NBOX; j += 1024) {
      float iw = fminf(ix2, bx2[j]) - fmaxf(ix1, bx1[j]);
      float ih = fminf(iy2, by2[j]) - fmaxf(iy1, by1[j]);
      iw = fmaxf(iw, 0.f);
      ih = fmaxf(ih, 0.f);
      float inter = iw * ih;
      float iou = inter / (ia + bar[j] - inter);
      if (iou >= 0.7f) atomicOr(&remv[j >> 6], 1ull << (j & 63));
    }
    cur = i + 1;
    if (count >= MAXDET) break;
    __syncthreads();
  }
  __syncthreads();
  for (int r = t; r < MAXDET; r += 1024) {
    float4 v = make_float4(0.f, 0.f, 0.f, 0.f);
    if (r < count) {
      int i = ssel[r];
      v = make_float4(bx1[i], by1[i], bx2[i], by2[i]);
    }
    *(float4*)&g_rois[r * 4] = v;
  }
}

// ---------------- K6: FC head on 300 ROIs + final outputs ----------------
__global__ __launch_bounds__(128) void fc_head_kernel(
    const float* __restrict__ fc1_w, const float* __restrict__ fc1_b,
    const float* __restrict__ clsh_w, const float* __restrict__ clsh_b,
    const float* __restrict__ regh_w, const float* __restrict__ regh_b,
    float* __restrict__ out) {
  const int r = blockIdx.x;
  const int t = threadIdx.x;
  float4 roi = *(const float4*)&g_rois[r * 4];
  float part[8];
#pragma unroll
  for (int o = 0; o < 8; o++) part[o] = 0.f;
  for (int j = t; j < 1024; j += 128) {
    float f = fc1_b[j] + roi.x * fc1_w[j] + roi.y * fc1_w[1024 + j] +
              roi.z * fc1_w[2048 + j] + roi.w * fc1_w[3072 + j];
    f = fmaxf(f, 0.f);
    float4 cw = *(const float4*)&clsh_w[j * 4];
    float4 rw = *(const float4*)&regh_w[j * 4];
    part[0] += f * cw.x; part[1] += f * cw.y; part[2] += f * cw.z; part[3] += f * cw.w;
    part[4] += f * rw.x; part[5] += f * rw.y; part[6] += f * rw.z; part[7] += f * rw.w;
  }
#pragma unroll
  for (int o = 0; o < 8; o++) {
#pragma unroll
    for (int s = 16; s > 0; s >>= 1) part[o] += __shfl_xor_sync(0xffffffffu, part[o], s);
  }
  __shared__ float wred[4][8];
  const int warp = t >> 5, lane = t & 31;
  if (lane == 0) {
#pragma unroll
    for (int o = 0; o < 8; o++) wred[warp][o] = part[o];
  }
  __syncthreads();
  if (t == 0) {
    float v[8];
#pragma unroll
    for (int o = 0; o < 8; o++) v[o] = wred[0][o] + wred[1][o] + wred[2][o] + wred[3][o];
    float l0 = v[0] + clsh_b[0], l1 = v[1] + clsh_b[1];
    float l2 = v[2] + clsh_b[2], l3 = v[3] + clsh_b[3];
    float mx = fmaxf(fmaxf(l0, l1), fmaxf(l2, l3));
    float e0 = expf(l0 - mx), e1 = expf(l1 - mx), e2 = expf(l2 - mx), e3 = expf(l3 - mx);
    float inv = 1.f / (e0 + e1 + e2 + e3);
    out[r * 4 + 0] = e0 * inv;
    out[r * 4 + 1] = e1 * inv;
    out[r * 4 + 2] = e2 * inv;
    out[r * 4 + 3] = e3 * inv;
    out[1200 + r * 4 + 0] = v[4] + regh_b[0];
    out[1200 + r * 4 + 1] = v[5] + regh_b[1];
    out[1200 + r * 4 + 2] = v[6] + regh_b[2];
    out[1200 + r * 4 + 3] = v[7] + regh_b[3];
    *(float4*)&out[2400 + r * 4] = roi;
  }
}

// ---------------- launch ----------------
extern "C" void kernel_launch(void* const* d_in, const int* in_sizes, int n_in,
                              void* d_out, int out_size) {
  const float* feat   = (const float*)d_in[0];
  const float* conv_w = (const float*)d_in[1];
  const float* conv_b = (const float*)d_in[2];
  const float* cls_w  = (const float*)d_in[3];
  const float* cls_b  = (const float*)d_in[4];
  const float* reg_w  = (const float*)d_in[5];
  const float* reg_b  = (const float*)d_in[6];
  const float* fc1_w  = (const float*)d_in[7];
  const float* fc1_b  = (const float*)d_in[8];
  const float* clsh_w = (const float*)d_in[9];
  const float* clsh_b = (const float*)d_in[10];
  const float* regh_w = (const float*)d_in[11];
  const float* regh_b = (const float*)d_in[12];
  float* out = (float*)d_out;

  (void)in_sizes; (void)n_in; (void)out_size;

  cudaFuncSetAttribute(conv_mma_kernel, cudaFuncAttributeMaxDynamicSharedMemorySize, SMEM_BYTES);
  cudaFuncSetAttribute(sort_kernel, cudaFuncAttributeMaxDynamicSharedMemorySize, 8192 * 8);
  cudaFuncSetAttribute(nms_kernel, cudaFuncAttributeMaxDynamicSharedMemorySize, NBOX * 5 * 4);

  feat_split_kernel<<<(NPIX * CIN) / 256, 256>>>(feat);
  w_split_kernel<<<dim3(9, CIN / 32, CMID / 32), dim3(32, 32)>>>(conv_w);
  conv_mma_kernel<<<dim3(13, 2, 9), 256, SMEM_BYTES>>>();
  reduce_bias_relu<<<1600, 256>>>(conv_b);
  head_conv_kernel<<<1600, 32>>>(cls_w, cls_b, reg_w, reg_b);
  sort_kernel<<<1, 1024, 8192 * 8>>>();
  nms_kernel<<<1, 1024, NBOX * 5 * 4>>>();
  fc_head_kernel<<<300, 128>>>(fc1_w, fc1_b, clsh_w, clsh_b, regh_w, regh_b, out);
}

// round 4
// speedup vs baseline: 1.1423x; 1.1423x over previous
#include <cuda_runtime.h>
#include <math.h>
#include <stdint.h>

#define HH 40
#define WW 40
#define CIN 2048
#define NPIX 1600
#define CMID 256
#define NA 5
#define NBOX 8000
#define NWORD 125
#define MAXDET 300
#define KC 16
#define NCH (CIN / KC)

// ---------------- device scratch (static, no allocation) ----------------
__device__ float g_partial[9 * NPIX * CMID];
__device__ float g_x[NPIX * CMID];
__device__ float g_scores[NBOX];
__device__ float g_boxes[NBOX * 4];
__device__ float g_boxsorted[NBOX * 4];
__device__ float g_rois[MAXDET * 4];

__device__ __forceinline__ uint32_t smem_u32(const void* p) {
  uint32_t a;
  asm("{ .reg .u64 t; cvta.to.shared.u64 t, %1; cvt.u32.u64 %0, t; }" : "=r"(a) : "l"(p));
  return a;
}
__device__ __forceinline__ void cp16(uint32_t dst, const void* src) {
  asm volatile("cp.async.ca.shared.global [%0], [%1], 16;" ::"r"(dst), "l"(src) : "memory");
}
#define CP_COMMIT() asm volatile("cp.async.commit_group;" ::: "memory")
#define CP_WAIT0() asm volatile("cp.async.wait_group 0;" ::: "memory")

// ---------------- K1: FFMA SGEMM conv, 64x128 tile, 8x4/thread ----------------
// grid (25 m-tiles, 2 n-tiles, 9 taps) = 450 blocks ~= 3/SM.
__global__ __launch_bounds__(256, 3) void conv_ffma_kernel(
    const float* __restrict__ feat, const float* __restrict__ wconv) {
  __shared__ __align__(16) float As[2][KC][64];    // 8 KB, k-major
  __shared__ __align__(16) float Bs[2][KC][128];   // 16 KB, k-major

  const int mt = blockIdx.x;
  const int nt = blockIdx.y;
  const int tap = blockIdx.z;
  const int ky = tap / 3, kx = tap % 3;
  const float* wt = wconv + (size_t)tap * CIN * CMID;  // [k][n]
  const int tid = threadIdx.x;
  const int warp = tid >> 5;
  const int lane = tid & 31;
  const int wm = warp & 1;   // m half (32 rows)
  const int wn = warp >> 1;  // n quarter (32 cols)
  const int tr = lane >> 3;  // 0..3
  const int tc = lane & 7;   // 0..7
  const int am_off = wm * 32 + tr * 8;   // fragment A row base (8 rows)
  const int bn_off = wn * 32 + tc * 4;   // fragment B col base (4 cols)

  // A global loader: thread -> pixel row (tid&63), k-group (tid>>6)*4
  const int am = tid & 63;
  const int akg = (tid >> 6) * 4;
  const int m = mt * 64 + am;
  const int y = m / WW, x = m % WW;
  const int py = y + ky - 1, px = x + kx - 1;
  const bool aval = (py >= 0 && py < HH && px >= 0 && px < WW);
  const float* arow = feat + (size_t)(aval ? (py * WW + px) : 0) * CIN + akg;

  // B loader: thread -> k row (tid>>4), n offset (tid&15)*8; 2x cp16
  const int bk = tid >> 4;
  const int bn = (tid & 15) * 8;
  const int n0 = nt * 128;
  const float* bsrc = wt + (size_t)bk * CMID + n0 + bn;

  float acc[8][4];
#pragma unroll
  for (int i = 0; i < 8; i++)
#pragma unroll
    for (int j = 0; j < 4; j++) acc[i][j] = 0.f;

  // prologue: chunk 0 -> buffer 0
  {
    float4 ra = aval ? *(const float4*)arow : make_float4(0.f, 0.f, 0.f, 0.f);
    cp16(smem_u32(&Bs[0][bk][bn]), bsrc);
    cp16(smem_u32(&Bs[0][bk][bn + 4]), bsrc + 4);
    CP_COMMIT();
    As[0][akg + 0][am] = ra.x;
    As[0][akg + 1][am] = ra.y;
    As[0][akg + 2][am] = ra.z;
    As[0][akg + 3][am] = ra.w;
    CP_WAIT0();
  }
  __syncthreads();

#pragma unroll 1
  for (int c = 0; c < NCH; c++) {
    const int cur = c & 1;
    const int nxtb = cur ^ 1;
    float4 ra;
    const bool more = (c + 1 < NCH);
    if (more) {
      const int k0 = (c + 1) * KC;
      ra = aval ? *(const float4*)(arow + k0) : make_float4(0.f, 0.f, 0.f, 0.f);
      const float* bs = bsrc + (size_t)k0 * CMID;
      cp16(smem_u32(&Bs[nxtb][bk][bn]), bs);
      cp16(smem_u32(&Bs[nxtb][bk][bn + 4]), bs + 4);
      CP_COMMIT();
    }
#pragma unroll
    for (int k = 0; k < KC; k++) {
      float4 a0 = *(const float4*)&As[cur][k][am_off];
      float4 a1 = *(const float4*)&As[cur][k][am_off + 4];
      float4 bv = *(const float4*)&Bs[cur][k][bn_off];
      float af[8] = {a0.x, a0.y, a0.z, a0.w, a1.x, a1.y, a1.z, a1.w};
      float bf[4] = {bv.x, bv.y, bv.z, bv.w};
#pragma unroll
      for (int i = 0; i < 8; i++)
#pragma unroll
        for (int j = 0; j < 4; j++) acc[i][j] = fmaf(af[i], bf[j], acc[i][j]);
    }
    if (more) {
      As[nxtb][akg + 0][am] = ra.x;
      As[nxtb][akg + 1][am] = ra.y;
      As[nxtb][akg + 2][am] = ra.z;
      As[nxtb][akg + 3][am] = ra.w;
      CP_WAIT0();
    }
    __syncthreads();
  }

  // epilogue: write 8x4 per thread (m always < 1600 since 25*64 = 1600)
  float* base = g_partial + (size_t)tap * (NPIX * CMID);
#pragma unroll
  for (int i = 0; i < 8; i++) {
    const int mr = mt * 64 + am_off + i;
    *(float4*)&base[(size_t)mr * CMID + n0 + bn_off] =
        make_float4(acc[i][0], acc[i][1], acc[i][2], acc[i][3]);
  }
}

// ---------------- K2: reduce 9 partials + bias + relu ----------------
__global__ __launch_bounds__(256) void reduce_bias_relu(const float* __restrict__ bias) {
  int i = blockIdx.x * 256 + threadIdx.x;
  float s = bias[i & 255];
#pragma unroll
  for (int t = 0; t < 9; t++) s += g_partial[(size_t)t * (NPIX * CMID) + i];
  g_x[i] = fmaxf(s, 0.f);
}

// ---------------- K3: 1x1 heads + score + anchor decode ----------------
__global__ __launch_bounds__(32) void head_conv_kernel(
    const float* __restrict__ cls_w, const float* __restrict__ cls_b,
    const float* __restrict__ reg_w, const float* __restrict__ reg_b) {
  const int p = blockIdx.x;
  const int lane = threadIdx.x;
  const float* xr = g_x + (size_t)p * CMID;
  float acc[30];
#pragma unroll
  for (int o = 0; o < 30; o++) acc[o] = 0.f;
  for (int k = lane; k < CMID; k += 32) {
    float xv = xr[k];
    const float* wc = cls_w + (size_t)k * 10;
#pragma unroll
    for (int o = 0; o < 10; o++) acc[o] = fmaf(xv, wc[o], acc[o]);
    const float* wr = reg_w + (size_t)k * 20;
#pragma unroll
    for (int o = 0; o < 20; o++) acc[10 + o] = fmaf(xv, wr[o], acc[10 + o]);
  }
#pragma unroll
  for (int o = 0; o < 30; o++) {
#pragma unroll
    for (int s = 16; s > 0; s >>= 1) acc[o] += __shfl_xor_sync(0xffffffffu, acc[o], s);
  }
  if (lane < NA) {
    const int a = lane;
    float l0 = acc[2 * a + 0] + cls_b[2 * a + 0];
    float l1 = acc[2 * a + 1] + cls_b[2 * a + 1];
    float score = 1.f / (1.f + expf(l0 - l1));
    float d0 = acc[10 + 4 * a + 0] + reg_b[4 * a + 0];
    float d1 = acc[10 + 4 * a + 1] + reg_b[4 * a + 1];
    float d2 = acc[10 + 4 * a + 2] + reg_b[4 * a + 2];
    float d3 = acc[10 + 4 * a + 3] + reg_b[4 * a + 3];
    float base = 32.f * (float)(1 << a);
    float wdt = expf(d2) * base;
    float hgt = expf(d3) * base;
    float xc = (float)(p % WW) + d0;
    float yc = (float)(p / WW) + d1;
    const int n = p * NA + a;
    g_scores[n] = score;
    float4 b = make_float4(xc - 0.5f * wdt, yc - 0.5f * hgt,
                           xc + 0.5f * wdt, yc + 0.5f * hgt);
    *(float4*)&g_boxes[n * 4] = b;
  }
}

// ---------------- K4: single-block bitonic sort of 8192 64-bit keys ----------------
__global__ __launch_bounds__(1024) void sort_kernel() {
  extern __shared__ unsigned long long skey[];
  const int t = threadIdx.x;
  for (int i = t; i < 8192; i += 1024) {
    unsigned long long kv;
    if (i < NBOX) {
      unsigned u = __float_as_uint(g_scores[i]);
      unsigned ou = (u & 0x80000000u) ? ~u : (u | 0x80000000u);
      kv = ((unsigned long long)(~ou) << 32) | (unsigned)i;
    } else {
      kv = 0xFFFFFFFFFFFFFFFFull;
    }
    skey[i] = kv;
  }
  __syncthreads();
  for (int k = 2; k <= 8192; k <<= 1) {
    for (int j = k >> 1; j > 0; j >>= 1) {
      for (int i = t; i < 8192; i += 1024) {
        int ixj = i ^ j;
        if (ixj > i) {
          unsigned long long a = skey[i], b = skey[ixj];
          bool up = (i & k) == 0;
          if ((a > b) == up) { skey[i] = b; skey[ixj] = a; }
        }
      }
      __syncthreads();
    }
  }
  for (int i = t; i < NBOX; i += 1024) {
    int idx = (int)(skey[i] & 0xFFFFFFFFull);
    *(float4*)&g_boxsorted[i * 4] = *(const float4*)&g_boxes[idx * 4];
  }
}

// ---------------- K5: greedy NMS ----------------
__global__ __launch_bounds__(1024) void nms_kernel() {
  extern __shared__ float sb[];
  float* bx1 = sb;
  float* by1 = sb + NBOX;
  float* bx2 = sb + 2 * NBOX;
  float* by2 = sb + 3 * NBOX;
  float* bar = sb + 4 * NBOX;
  __shared__ unsigned long long remv[NWORD];
  __shared__ int ssel[MAXDET];
  __shared__ int s_next;
  const int t = threadIdx.x;
  for (int i = t; i < NBOX; i += 1024) {
    float4 b = *(const float4*)&g_boxsorted[i * 4];
    bx1[i] = b.x; by1[i] = b.y; bx2[i] = b.z; by2[i] = b.w;
    bar[i] = (b.z - b.x) * (b.w - b.y);
  }
  if (t < NWORD) remv[t] = 0ull;
  __syncthreads();

  int count = 0, cur = 0;
  for (;;) {
    if (t == 0) s_next = 0x7FFFFFFF;
    __syncthreads();
    const int wstart = cur >> 6;
    if (t >= wstart && t < NWORD) {
      unsigned long long mw = ~remv[t];
      if (t == wstart) mw &= (~0ull) << (cur & 63);
      if (mw) atomicMin(&s_next, (t << 6) + (__ffsll((long long)mw) - 1));
    }
    __syncthreads();
    const int i = s_next;
    if (i == 0x7FFFFFFF) break;
    if (t == 0) ssel[count] = i;
    count++;
    const float ix1 = bx1[i], iy1 = by1[i], ix2 = bx2[i], iy2 = by2[i], ia = bar[i];
    for (int j = i + 1 + t; j < NBOX; j += 1024) {
      float iw = fminf(ix2, bx2[j]) - fmaxf(ix1, bx1[j]);
      float ih = fminf(iy2, by2[j]) - fmaxf(iy1, by1[j]);
      iw = fmaxf(iw, 0.f);
      ih = fmaxf(ih, 0.f);
      float inter = iw * ih;
      float iou = inter / (ia + bar[j] - inter);
      if (iou >= 0.7f) atomicOr(&remv[j >> 6], 1ull << (j & 63));
    }
    cur = i + 1;
    if (count >= MAXDET) break;
    __syncthreads();
  }
  __syncthreads();
  for (int r = t; r < MAXDET; r += 1024) {
    float4 v = make_float4(0.f, 0.f, 0.f, 0.f);
    if (r < count) {
      int i = ssel[r];
      v = make_float4(bx1[i], by1[i], bx2[i], by2[i]);
    }
    *(float4*)&g_rois[r * 4] = v;
  }
}

// ---------------- K6: FC head on 300 ROIs + final outputs ----------------
__global__ __launch_bounds__(128) void fc_head_kernel(
    const float* __restrict__ fc1_w, const float* __restrict__ fc1_b,
    const float* __restrict__ clsh_w, const float* __restrict__ clsh_b,
    const float* __restrict__ regh_w, const float* __restrict__ regh_b,
    float* __restrict__ out) {
  const int r = blockIdx.x;
  const int t = threadIdx.x;
  float4 roi = *(const float4*)&g_rois[r * 4];
  float part[8];
#pragma unroll
  for (int o = 0; o < 8; o++) part[o] = 0.f;
  for (int j = t; j < 1024; j += 128) {
    float f = fc1_b[j] + roi.x * fc1_w[j] + roi.y * fc1_w[1024 + j] +
              roi.z * fc1_w[2048 + j] + roi.w * fc1_w[3072 + j];
    f = fmaxf(f, 0.f);
    float4 cw = *(const float4*)&clsh_w[j * 4];
    float4 rw = *(const float4*)&regh_w[j * 4];
    part[0] += f * cw.x; part[1] += f * cw.y; part[2] += f * cw.z; part[3] += f * cw.w;
    part[4] += f * rw.x; part[5] += f * rw.y; part[6] += f * rw.z; part[7] += f * rw.w;
  }
#pragma unroll
  for (int o = 0; o < 8; o++) {
#pragma unroll
    for (int s = 16; s > 0; s >>= 1) part[o] += __shfl_xor_sync(0xffffffffu, part[o], s);
  }
  __shared__ float wred[4][8];
  const int warp = t >> 5, lane = t & 31;
  if (lane == 0) {
#pragma unroll
    for (int o = 0; o < 8; o++) wred[warp][o] = part[o];
  }
  __syncthreads();
  if (t == 0) {
    float v[8];
#pragma unroll
    for (int o = 0; o < 8; o++) v[o] = wred[0][o] + wred[1][o] + wred[2][o] + wred[3][o];
    float l0 = v[0] + clsh_b[0], l1 = v[1] + clsh_b[1];
    float l2 = v[2] + clsh_b[2], l3 = v[3] + clsh_b[3];
    float mx = fmaxf(fmaxf(l0, l1), fmaxf(l2, l3));
    float e0 = expf(l0 - mx), e1 = expf(l1 - mx), e2 = expf(l2 - mx), e3 = expf(l3 - mx);
    float inv = 1.f / (e0 + e1 + e2 + e3);
    out[r * 4 + 0] = e0 * inv;
    out[r * 4 + 1] = e1 * inv;
    out[r * 4 + 2] = e2 * inv;
    out[r * 4 + 3] = e3 * inv;
    out[1200 + r * 4 + 0] = v[4] + regh_b[0];
    out[1200 + r * 4 + 1] = v[5] + regh_b[1];
    out[1200 + r * 4 + 2] = v[6] + regh_b[2];
    out[1200 + r * 4 + 3] = v[7] + regh_b[3];
    *(float4*)&out[2400 + r * 4] = roi;
  }
}

// ---------------- launch ----------------
extern "C" void kernel_launch(void* const* d_in, const int* in_sizes, int n_in,
                              void* d_out, int out_size) {
  const float* feat   = (const float*)d_in[0];
  const float* conv_w = (const float*)d_in[1];
  const float* conv_b = (const float*)d_in[2];
  const float* cls_w  = (const float*)d_in[3];
  const float* cls_b  = (const float*)d_in[4];
  const float* reg_w  = (const float*)d_in[5];
  const float* reg_b  = (const float*)d_in[6];
  const float* fc1_w  = (const float*)d_in[7];
  const float* fc1_b  = (const float*)d_in[8];
  const float* clsh_w = (const float*)d_in[9];
  const float* clsh_b = (const float*)d_in[10];
  const float* regh_w = (const float*)d_in[11];
  const float* regh_b = (const float*)d_in[12];
  float* out = (float*)d_out;

  (void)in_sizes; (void)n_in; (void)out_size;

  cudaFuncSetAttribute(sort_kernel, cudaFuncAttributeMaxDynamicSharedMemorySize, 8192 * 8);
  cudaFuncSetAttribute(nms_kernel, cudaFuncAttributeMaxDynamicSharedMemorySize, NBOX * 5 * 4);

  conv_ffma_kernel<<<dim3(25, 2, 9), 256>>>(feat, conv_w);
  reduce_bias_relu<<<1600, 256>>>(conv_b);
  head_conv_kernel<<<1600, 32>>>(cls_w, cls_b, reg_w, reg_b);
  sort_kernel<<<1, 1024, 8192 * 8>>>();
  nms_kernel<<<1, 1024, NBOX * 5 * 4>>>();
  fc_head_kernel<<<300, 128>>>(fc1_w, fc1_b, clsh_w, clsh_b, regh_w, regh_b, out);
}

// round 5
// speedup vs baseline: 1.1446x; 1.0020x over previous
#include <cuda_runtime.h>
#include <math.h>
#include <stdint.h>

#define HH 40
#define WW 40
#define CIN 2048
#define NPIX 1600
#define CMID 256
#define NA 5
#define NBOX 8000
#define NWORD 125
#define MAXDET 300

#define KSLICES 2
#define KPS (CIN / KSLICES)  // 1024 k per slice
#define KC2 32
#define NCH2 (KPS / KC2)     // 32 chunks
#define NPLANE (9 * KSLICES) // 18 partial planes

// ---------------- device scratch (static, no allocation) ----------------
__device__ float g_partial[NPLANE * NPIX * CMID];
__device__ float g_x[NPIX * CMID];
__device__ float g_scores[NBOX];
__device__ float g_boxes[NBOX * 4];
__device__ float g_boxsorted[NBOX * 4];
__device__ float g_rois[MAXDET * 4];

__device__ __forceinline__ uint32_t smem_u32(const void* p) {
  uint32_t a;
  asm("{ .reg .u64 t; cvta.to.shared.u64 t, %1; cvt.u32.u64 %0, t; }" : "=r"(a) : "l"(p));
  return a;
}
__device__ __forceinline__ void cp16(uint32_t dst, const void* src) {
  asm volatile("cp.async.ca.shared.global [%0], [%1], 16;" ::"r"(dst), "l"(src) : "memory");
}
#define CP_COMMIT() asm volatile("cp.async.commit_group;" ::: "memory")
#define CP_WAIT0() asm volatile("cp.async.wait_group 0;" ::: "memory")

// packed fp32x2 fma: d.lo = a.lo*b.lo + d.lo ; d.hi likewise
#define FMA2(c, a, b) \
  asm("fma.rn.f32x2 %0, %1, %2, %0;" : "+l"(c) : "l"(a), "l"(b))
__device__ __forceinline__ unsigned long long dup2(float f) {
  unsigned long long r;
  uint32_t u = __float_as_uint(f);
  asm("mov.b64 %0, {%1, %1};" : "=l"(r) : "r"(u));
  return r;
}
__device__ __forceinline__ float lo32(unsigned long long v) {
  return __uint_as_float((uint32_t)(v & 0xFFFFFFFFull));
}
__device__ __forceinline__ float hi32(unsigned long long v) {
  return __uint_as_float((uint32_t)(v >> 32));
}

// ---------------- K1: f32x2 SGEMM conv, 64x128 tile, (tap,k-slice) split ----------------
// grid (25 m-tiles, 2 n-tiles, 18 tap-slices) = 900 blocks.
__global__ __launch_bounds__(256) void conv_f32x2_kernel(
    const float* __restrict__ feat, const float* __restrict__ wconv) {
  __shared__ __align__(16) float As[2][KC2][64];    // 16 KB, k-major
  __shared__ __align__(16) float Bs[2][KC2][128];   // 32 KB, k-major

  const int mt = blockIdx.x;
  const int nt = blockIdx.y;
  const int tz = blockIdx.z;       // 0..17
  const int tap = tz >> 1;
  const int ks = tz & 1;
  const int ky = tap / 3, kx = tap % 3;
  const int tid = threadIdx.x;
  const int warp = tid >> 5;
  const int lane = tid & 31;
  const int wm = warp & 1;
  const int wn = warp >> 1;
  const int tr = lane >> 3;
  const int tc = lane & 7;
  const int am_off = wm * 32 + tr * 8;   // 8 m-rows (4 packed pairs)
  const int bn_off = wn * 32 + tc * 4;   // 4 n-cols

  // A loader: pixel row am (0..63), k-group akg (two float4 at +0, +16)
  const int am = tid & 63;
  const int akg = (tid >> 6) * 4;
  const int m = mt * 64 + am;
  const int y = m / WW, x = m % WW;
  const int py = y + ky - 1, px = x + kx - 1;
  const bool aval = (py >= 0 && py < HH && px >= 0 && px < WW);
  const float* arow = feat + (size_t)(aval ? (py * WW + px) : 0) * CIN + ks * KPS + akg;

  // B loader: k-row bk (0..31), n-offset bn (4x cp16)
  const int bk = tid >> 3;
  const int bn = (tid & 7) * 16;
  const int n0 = nt * 128;
  const float* bsrc =
      wconv + (size_t)tap * CIN * CMID + (size_t)(ks * KPS + bk) * CMID + n0 + bn;

  unsigned long long acc2[4][4];
#pragma unroll
  for (int i = 0; i < 4; i++)
#pragma unroll
    for (int j = 0; j < 4; j++) acc2[i][j] = 0ull;

  // prologue: chunk 0 -> buffer 0
  {
    float4 ra0 = aval ? *(const float4*)arow : make_float4(0.f, 0.f, 0.f, 0.f);
    float4 ra1 = aval ? *(const float4*)(arow + 16) : make_float4(0.f, 0.f, 0.f, 0.f);
#pragma unroll
    for (int i = 0; i < 4; i++) cp16(smem_u32(&Bs[0][bk][bn + i * 4]), bsrc + i * 4);
    CP_COMMIT();
    As[0][akg + 0][am] = ra0.x;
    As[0][akg + 1][am] = ra0.y;
    As[0][akg + 2][am] = ra0.z;
    As[0][akg + 3][am] = ra0.w;
    As[0][akg + 16][am] = ra1.x;
    As[0][akg + 17][am] = ra1.y;
    As[0][akg + 18][am] = ra1.z;
    As[0][akg + 19][am] = ra1.w;
    CP_WAIT0();
  }
  __syncthreads();

#pragma unroll 1
  for (int c = 0; c < NCH2; c++) {
    const int cur = c & 1;
    const int nxtb = cur ^ 1;
    float4 ra0, ra1;
    const bool more = (c + 1 < NCH2);
    if (more) {
      const int k0 = (c + 1) * KC2;
      ra0 = aval ? *(const float4*)(arow + k0) : make_float4(0.f, 0.f, 0.f, 0.f);
      ra1 = aval ? *(const float4*)(arow + k0 + 16) : make_float4(0.f, 0.f, 0.f, 0.f);
      const float* bs = bsrc + (size_t)k0 * CMID;
#pragma unroll
      for (int i = 0; i < 4; i++) cp16(smem_u32(&Bs[nxtb][bk][bn + i * 4]), bs + i * 4);
      CP_COMMIT();
    }
#pragma unroll
    for (int k = 0; k < KC2; k++) {
      ulonglong2 a01 = *(const ulonglong2*)&As[cur][k][am_off];
      ulonglong2 a23 = *(const ulonglong2*)&As[cur][k][am_off + 4];
      float4 bv = *(const float4*)&Bs[cur][k][bn_off];
      unsigned long long ap[4] = {a01.x, a01.y, a23.x, a23.y};
      unsigned long long b2[4] = {dup2(bv.x), dup2(bv.y), dup2(bv.z), dup2(bv.w)};
#pragma unroll
      for (int i = 0; i < 4; i++)
#pragma unroll
        for (int j = 0; j < 4; j++) FMA2(acc2[i][j], ap[i], b2[j]);
    }
    if (more) {
      As[nxtb][akg + 0][am] = ra0.x;
      As[nxtb][akg + 1][am] = ra0.y;
      As[nxtb][akg + 2][am] = ra0.z;
      As[nxtb][akg + 3][am] = ra0.w;
      As[nxtb][akg + 16][am] = ra1.x;
      As[nxtb][akg + 17][am] = ra1.y;
      As[nxtb][akg + 18][am] = ra1.z;
      As[nxtb][akg + 19][am] = ra1.w;
      CP_WAIT0();
    }
    __syncthreads();
  }

  // epilogue: unpack, write 8 rows x 4 cols per thread
  float* base = g_partial + (size_t)tz * (NPIX * CMID);
#pragma unroll
  for (int i = 0; i < 4; i++) {
    const int mr = mt * 64 + am_off + 2 * i;
    *(float4*)&base[(size_t)mr * CMID + n0 + bn_off] =
        make_float4(lo32(acc2[i][0]), lo32(acc2[i][1]), lo32(acc2[i][2]), lo32(acc2[i][3]));
    *(float4*)&base[(size_t)(mr + 1) * CMID + n0 + bn_off] =
        make_float4(hi32(acc2[i][0]), hi32(acc2[i][1]), hi32(acc2[i][2]), hi32(acc2[i][3]));
  }
}

// ---------------- K2: reduce 18 partials + bias + relu ----------------
__global__ __launch_bounds__(256) void reduce_bias_relu(const float* __restrict__ bias) {
  int i = blockIdx.x * 256 + threadIdx.x;
  float s = bias[i & 255];
#pragma unroll
  for (int t = 0; t < NPLANE; t++) s += g_partial[(size_t)t * (NPIX * CMID) + i];
  g_x[i] = fmaxf(s, 0.f);
}

// ---------------- K3: 1x1 heads + score + anchor decode ----------------
__global__ __launch_bounds__(32) void head_conv_kernel(
    const float* __restrict__ cls_w, const float* __restrict__ cls_b,
    const float* __restrict__ reg_w, const float* __restrict__ reg_b) {
  const int p = blockIdx.x;
  const int lane = threadIdx.x;
  const float* xr = g_x + (size_t)p * CMID;
  float acc[30];
#pragma unroll
  for (int o = 0; o < 30; o++) acc[o] = 0.f;
  for (int k = lane; k < CMID; k += 32) {
    float xv = xr[k];
    const float* wc = cls_w + (size_t)k * 10;
#pragma unroll
    for (int o = 0; o < 10; o++) acc[o] = fmaf(xv, wc[o], acc[o]);
    const float* wr = reg_w + (size_t)k * 20;
#pragma unroll
    for (int o = 0; o < 20; o++) acc[10 + o] = fmaf(xv, wr[o], acc[10 + o]);
  }
#pragma unroll
  for (int o = 0; o < 30; o++) {
#pragma unroll
    for (int s = 16; s > 0; s >>= 1) acc[o] += __shfl_xor_sync(0xffffffffu, acc[o], s);
  }
  if (lane < NA) {
    const int a = lane;
    float l0 = acc[2 * a + 0] + cls_b[2 * a + 0];
    float l1 = acc[2 * a + 1] + cls_b[2 * a + 1];
    float score = 1.f / (1.f + expf(l0 - l1));
    float d0 = acc[10 + 4 * a + 0] + reg_b[4 * a + 0];
    float d1 = acc[10 + 4 * a + 1] + reg_b[4 * a + 1];
    float d2 = acc[10 + 4 * a + 2] + reg_b[4 * a + 2];
    float d3 = acc[10 + 4 * a + 3] + reg_b[4 * a + 3];
    float base = 32.f * (float)(1 << a);
    float wdt = expf(d2) * base;
    float hgt = expf(d3) * base;
    float xc = (float)(p % WW) + d0;
    float yc = (float)(p / WW) + d1;
    const int n = p * NA + a;
    g_scores[n] = score;
    float4 b = make_float4(xc - 0.5f * wdt, yc - 0.5f * hgt,
                           xc + 0.5f * wdt, yc + 0.5f * hgt);
    *(float4*)&g_boxes[n * 4] = b;
  }
}

// ---------------- K4: single-block bitonic sort of 8192 64-bit keys ----------------
__global__ __launch_bounds__(1024) void sort_kernel() {
  extern __shared__ unsigned long long skey[];
  const int t = threadIdx.x;
  for (int i = t; i < 8192; i += 1024) {
    unsigned long long kv;
    if (i < NBOX) {
      unsigned u = __float_as_uint(g_scores[i]);
      unsigned ou = (u & 0x80000000u) ? ~u : (u | 0x80000000u);
      kv = ((unsigned long long)(~ou) << 32) | (unsigned)i;
    } else {
      kv = 0xFFFFFFFFFFFFFFFFull;
    }
    skey[i] = kv;
  }
  __syncthreads();
  for (int k = 2; k <= 8192; k <<= 1) {
    for (int j = k >> 1; j > 0; j >>= 1) {
      for (int i = t; i < 8192; i += 1024) {
        int ixj = i ^ j;
        if (ixj > i) {
          unsigned long long a = skey[i], b = skey[ixj];
          bool up = (i & k) == 0;
          if ((a > b) == up) { skey[i] = b; skey[ixj] = a; }
        }
      }
      __syncthreads();
    }
  }
  for (int i = t; i < NBOX; i += 1024) {
    int idx = (int)(skey[i] & 0xFFFFFFFFull);
    *(float4*)&g_boxsorted[i * 4] = *(const float4*)&g_boxes[idx * 4];
  }
}

// ---------------- K5: greedy NMS ----------------
__global__ __launch_bounds__(1024) void nms_kernel() {
  extern __shared__ float sb[];
  float* bx1 = sb;
  float* by1 = sb + NBOX;
  float* bx2 = sb + 2 * NBOX;
  float* by2 = sb + 3 * NBOX;
  float* bar = sb + 4 * NBOX;
  __shared__ unsigned long long remv[NWORD];
  __shared__ int ssel[MAXDET];
  __shared__ int s_next;
  const int t = threadIdx.x;
  for (int i = t; i < NBOX; i += 1024) {
    float4 b = *(const float4*)&g_boxsorted[i * 4];
    bx1[i] = b.x; by1[i] = b.y; bx2[i] = b.z; by2[i] = b.w;
    bar[i] = (b.z - b.x) * (b.w - b.y);
  }
  if (t < NWORD) remv[t] = 0ull;
  __syncthreads();

  int count = 0, cur = 0;
  for (;;) {
    if (t == 0) s_next = 0x7FFFFFFF;
    __syncthreads();
    const int wstart = cur >> 6;
    if (t >= wstart && t < NWORD) {
      unsigned long long mw = ~remv[t];
      if (t == wstart) mw &= (~0ull) << (cur & 63);
      if (mw) atomicMin(&s_next, (t << 6) + (__ffsll((long long)mw) - 1));
    }
    __syncthreads();
    const int i = s_next;
    if (i == 0x7FFFFFFF) break;
    if (t == 0) ssel[count] = i;
    count++;
    const float ix1 = bx1[i], iy1 = by1[i], ix2 = bx2[i], iy2 = by2[i], ia = bar[i];
    for (int j = i + 1 + t; j < NBOX; j += 1024) {
      float iw = fminf(ix2, bx2[j]) - fmaxf(ix1, bx1[j]);
      float ih = fminf(iy2, by2[j]) - fmaxf(iy1, by1[j]);
      iw = fmaxf(iw, 0.f);
      ih = fmaxf(ih, 0.f);
      float inter = iw * ih;
      float iou = inter / (ia + bar[j] - inter);
      if (iou >= 0.7f) atomicOr(&remv[j >> 6], 1ull << (j & 63));
    }
    cur = i + 1;
    if (count >= MAXDET) break;
    __syncthreads();
  }
  __syncthreads();
  for (int r = t; r < MAXDET; r += 1024) {
    float4 v = make_float4(0.f, 0.f, 0.f, 0.f);
    if (r < count) {
      int i = ssel[r];
      v = make_float4(bx1[i], by1[i], bx2[i], by2[i]);
    }
    *(float4*)&g_rois[r * 4] = v;
  }
}

// ---------------- K6: FC head on 300 ROIs + final outputs ----------------
__global__ __launch_bounds__(128) void fc_head_kernel(
    const float* __restrict__ fc1_w, const float* __restrict__ fc1_b,
    const float* __restrict__ clsh_w, const float* __restrict__ clsh_b,
    const float* __restrict__ regh_w, const float* __restrict__ regh_b,
    float* __restrict__ out) {
  const int r = blockIdx.x;
  const int t = threadIdx.x;
  float4 roi = *(const float4*)&g_rois[r * 4];
  float part[8];
#pragma unroll
  for (int o = 0; o < 8; o++) part[o] = 0.f;
  for (int j = t; j < 1024; j += 128) {
    float f = fc1_b[j] + roi.x * fc1_w[j] + roi.y * fc1_w[1024 + j] +
              roi.z * fc1_w[2048 + j] + roi.w * fc1_w[3072 + j];
    f = fmaxf(f, 0.f);
    float4 cw = *(const float4*)&clsh_w[j * 4];
    float4 rw = *(const float4*)&regh_w[j * 4];
    part[0] += f * cw.x; part[1] += f * cw.y; part[2] += f * cw.z; part[3] += f * cw.w;
    part[4] += f * rw.x; part[5] += f * rw.y; part[6] += f * rw.z; part[7] += f * rw.w;
  }
#pragma unroll
  for (int o = 0; o < 8; o++) {
#pragma unroll
    for (int s = 16; s > 0; s >>= 1) part[o] += __shfl_xor_sync(0xffffffffu, part[o], s);
  }
  __shared__ float wred[4][8];
  const int warp = t >> 5, lane = t & 31;
  if (lane == 0) {
#pragma unroll
    for (int o = 0; o < 8; o++) wred[warp][o] = part[o];
  }
  __syncthreads();
  if (t == 0) {
    float v[8];
#pragma unroll
    for (int o = 0; o < 8; o++) v[o] = wred[0][o] + wred[1][o] + wred[2][o] + wred[3][o];
    float l0 = v[0] + clsh_b[0], l1 = v[1] + clsh_b[1];
    float l2 = v[2] + clsh_b[2], l3 = v[3] + clsh_b[3];
    float mx = fmaxf(fmaxf(l0, l1), fmaxf(l2, l3));
    float e0 = expf(l0 - mx), e1 = expf(l1 - mx), e2 = expf(l2 - mx), e3 = expf(l3 - mx);
    float inv = 1.f / (e0 + e1 + e2 + e3);
    out[r * 4 + 0] = e0 * inv;
    out[r * 4 + 1] = e1 * inv;
    out[r * 4 + 2] = e2 * inv;
    out[r * 4 + 3] = e3 * inv;
    out[1200 + r * 4 + 0] = v[4] + regh_b[0];
    out[1200 + r * 4 + 1] = v[5] + regh_b[1];
    out[1200 + r * 4 + 2] = v[6] + regh_b[2];
    out[1200 + r * 4 + 3] = v[7] + regh_b[3];
    *(float4*)&out[2400 + r * 4] = roi;
  }
}

// ---------------- launch ----------------
extern "C" void kernel_launch(void* const* d_in, const int* in_sizes, int n_in,
                              void* d_out, int out_size) {
  const float* feat   = (const float*)d_in[0];
  const float* conv_w = (const float*)d_in[1];
  const float* conv_b = (const float*)d_in[2];
  const float* cls_w  = (const float*)d_in[3];
  const float* cls_b  = (const float*)d_in[4];
  const float* reg_w  = (const float*)d_in[5];
  const float* reg_b  = (const float*)d_in[6];
  const float* fc1_w  = (const float*)d_in[7];
  const float* fc1_b  = (const float*)d_in[8];
  const float* clsh_w = (const float*)d_in[9];
  const float* clsh_b = (const float*)d_in[10];
  const float* regh_w = (const float*)d_in[11];
  const float* regh_b = (const float*)d_in[12];
  float* out = (float*)d_out;

  (void)in_sizes; (void)n_in; (void)out_size;

  cudaFuncSetAttribute(sort_kernel, cudaFuncAttributeMaxDynamicSharedMemorySize, 8192 * 8);
  cudaFuncSetAttribute(nms_kernel, cudaFuncAttributeMaxDynamicSharedMemorySize, NBOX * 5 * 4);

  conv_f32x2_kernel<<<dim3(25, 2, NPLANE), 256>>>(feat, conv_w);
  reduce_bias_relu<<<1600, 256>>>(conv_b);
  head_conv_kernel<<<1600, 32>>>(cls_w, cls_b, reg_w, reg_b);
  sort_kernel<<<1, 1024, 8192 * 8>>>();
  nms_kernel<<<1, 1024, NBOX * 5 * 4>>>();
  fc_head_kernel<<<300, 128>>>(fc1_w, fc1_b, clsh_w, clsh_b, regh_w, regh_b, out);
}